// round 4
// baseline (speedup 1.0000x reference)
#include <cuda_runtime.h>
#include <cuda_fp16.h>
#include <cstdint>

// ---------------------------------------------------------------------------
// SparseBlock 3x3 valid conv + BN + ReLU as implicit GEMM on baseline-ISA
// tensor cores (mma.sync.m16n8k16.f32.f16.f16.f32 + ldmatrix).
// Persistent CTAs (grid-stride over groups of 4 blocks), double-buffered
// gather overlapped with the MMA mainloop, weight image loaded to smem once.
// ---------------------------------------------------------------------------

namespace {
constexpr int H = 400, W = 400, C = 64, CO = 64;
constexpr int BST = 8;
constexpr int HOUT = 398, WOUT = 398;
constexpr float EPS = 1e-3f;

constexpr int KP = 584;                    // padded B row (halves); 1168B = 73*16B (odd mod 8)
constexpr int B_BYTES = 64 * KP * 2;       // 74752
constexpr int SM_SC   = 0;                 // 64 floats (BN scale)
constexpr int SM_BI   = 256;               // 64 floats (BN bias)
constexpr int SM_B    = 512;               // weight image
constexpr int SM_TILE = SM_B + B_BYTES;    // 75264
constexpr int TILE_STRIDE = 144;           // bytes per position row (9*16B, odd mod 8)
constexpr int TILE_B  = 100 * TILE_STRIDE; // 14400 per block
constexpr int BUF_B   = 4 * TILE_B;        // 57600 per group buffer
constexpr int SMEM_TOTAL = SM_TILE + 2 * BUF_B;  // 190464

__device__ __forceinline__ uint32_t smem_u32(const void* p) {
    uint32_t a;
    asm("{ .reg .u64 t; cvta.to.shared.u64 t, %1; cvt.u32.u64 %0, t; }"
        : "=r"(a) : "l"(p));
    return a;
}
__device__ __forceinline__ void ldsm_x4(uint32_t* r, uint32_t addr) {
    asm volatile("ldmatrix.sync.aligned.m8n8.x4.shared.b16 {%0,%1,%2,%3}, [%4];"
                 : "=r"(r[0]), "=r"(r[1]), "=r"(r[2]), "=r"(r[3]) : "r"(addr));
}
__device__ __forceinline__ void mma16816(float* d, const uint32_t* a,
                                         uint32_t b0, uint32_t b1) {
    asm volatile(
        "mma.sync.aligned.m16n8k16.row.col.f32.f16.f16.f32 "
        "{%0,%1,%2,%3},{%4,%5,%6,%7},{%8,%9},{%0,%1,%2,%3};"
        : "+f"(d[0]), "+f"(d[1]), "+f"(d[2]), "+f"(d[3])
        : "r"(a[0]), "r"(a[1]), "r"(a[2]), "r"(a[3]), "r"(b0), "r"(b1));
}

// One gather chunk: 256 threads move chunk k (of 25) of a 4-block group
// (fp32 global -> fp16 smem tile, row stride 144 B).
__device__ __forceinline__ void gather_chunk(
    unsigned char* smem, int bufbase, int t, int k,
    const float* x0, const float* x1, const float* x2, const float* x3) {
    int i = t + 256 * k;                  // 0..6399
    int tile = i / 1600;
    int j = i - tile * 1600;
    int pos = j >> 4;                     // 0..99
    int c4  = j & 15;
    int ph = pos / 10, pw = pos - (pos / 10) * 10;
    const float* xp = (tile == 0) ? x0 : (tile == 1) ? x1 : (tile == 2) ? x2 : x3;
    float4 v = __ldcs(reinterpret_cast<const float4*>(xp + (ph * W + pw) * C + c4 * 4));
    __half2 h0 = __floats2half2_rn(v.x, v.y);
    __half2 h1 = __floats2half2_rn(v.z, v.w);
    uint2 pk = make_uint2(*reinterpret_cast<uint32_t*>(&h0),
                          *reinterpret_cast<uint32_t*>(&h1));
    *reinterpret_cast<uint2*>(smem + bufbase + tile * TILE_B
                              + pos * TILE_STRIDE + c4 * 8) = pk;
}
} // namespace

// Pre-converted fp16 weight image [cout][k], row stride KP halves.
__device__ __align__(16) unsigned char g_wB[B_BYTES];

__global__ void wprep_kernel(const float* __restrict__ wgt) {
    int i = blockIdx.x * 256 + threadIdx.x;
    if (i >= 9 * 64 * 64) return;
    int cout = i & 63;
    int cin  = (i >> 6) & 63;
    int s    = i >> 12;
    reinterpret_cast<__half*>(g_wB)[cout * KP + s * 64 + cin] = __float2half(wgt[i]);
}

__global__ void zero_kernel(float4* __restrict__ o4, int n4) {
    int i = blockIdx.x * blockDim.x + threadIdx.x;
    int stride = gridDim.x * blockDim.x;
    const float4 z = make_float4(0.f, 0.f, 0.f, 0.f);
    for (; i < n4; i += stride) o4[i] = z;
}

// ---------------------------------------------------------------------------
__global__ __launch_bounds__(256)
void conv_kernel(const float* __restrict__ x,
                 const float* __restrict__ convb,
                 const float* __restrict__ gamma,
                 const float* __restrict__ beta,
                 const float* __restrict__ mean,
                 const float* __restrict__ var,
                 const int*   __restrict__ idx,
                 float* __restrict__ out,
                 int nb) {
    extern __shared__ __align__(16) unsigned char smem[];
    const uint32_t sb = smem_u32(smem);
    const int t = threadIdx.x;
    const int lane = t & 31;
    const int warp = t >> 5;
    const int ngroups = (nb + 3) >> 2;

    // BN fold
    if (t < 64) {
        float s = gamma[t] * rsqrtf(var[t] + EPS);
        reinterpret_cast<float*>(smem + SM_SC)[t] = s;
        reinterpret_cast<float*>(smem + SM_BI)[t] = fmaf(convb[t] - mean[t], s, beta[t]);
    }

    // B image -> smem once per (persistent) CTA: 74752 B = 4672 uint4
    {
        const uint4* src = reinterpret_cast<const uint4*>(g_wB);
        uint4* dst = reinterpret_cast<uint4*>(smem + SM_B);
        #pragma unroll
        for (int k = 0; k < 19; k++) {
            int i = t + 256 * k;
            if (i < 4672) dst[i] = src[i];
        }
    }

    // ---- per-warp constant addressing ----
    const int bidx  = warp >> 1;   // block within group (0..3)
    const int mhalf = warp & 1;    // rows 0-31 / 32-63 of the block
    // A lane offsets within a tile (per m16 subtile)
    uint32_t a_off[2];
    #pragma unroll
    for (int mt = 0; mt < 2; mt++) {
        int r = (lane & 15) + mt * 16;
        int pos = mhalf * 32 + r;
        int h = pos >> 3, w = pos & 7;
        a_off[mt] = (h * 10 + w) * TILE_STRIDE + (lane >> 4) * 16;
    }
    const uint32_t bn = (lane & 7) + ((lane >> 4) << 3);
    const uint32_t b_addr = sb + SM_B + bn * (KP * 2) + ((lane >> 3) & 1) * 16;
    const int soff[9] = {0, 1, 2, 10, 11, 12, 20, 21, 22};

    // helper to fetch the 4 block base pointers for a group
    auto group_ptrs = [&](int g, const float*& p0, const float*& p1,
                          const float*& p2, const float*& p3) {
        const float* p[4];
        #pragma unroll
        for (int b = 0; b < 4; b++) {
            int gb = g * 4 + b;
            if (gb < nb) {
                int n  = __ldg(idx + gb * 3 + 0);
                int by = __ldg(idx + gb * 3 + 1);
                int bx = __ldg(idx + gb * 3 + 2);
                p[b] = x + ((n * H + by * BST) * W + bx * BST) * C;
            } else p[b] = x;
        }
        p0 = p[0]; p1 = p[1]; p2 = p[2]; p3 = p[3];
    };

    // ---- prologue: gather first group into buffer 0 ----
    int group = blockIdx.x;
    if (group < ngroups) {
        const float *x0, *x1, *x2, *x3;
        group_ptrs(group, x0, x1, x2, x3);
        #pragma unroll
        for (int k = 0; k < 25; k++)
            gather_chunk(smem, SM_TILE, t, k, x0, x1, x2, x3);
    }
    __syncthreads();

    int buf = 0;
    while (group < ngroups) {
        const int next = group + gridDim.x;
        const bool has_next = next < ngroups;
        const float *n0 = x, *n1 = x, *n2 = x, *n3 = x;
        if (has_next) group_ptrs(next, n0, n1, n2, n3);

        const uint32_t tbase = sb + SM_TILE + buf * BUF_B + bidx * TILE_B;
        const int nxtbase = SM_TILE + (buf ^ 1) * BUF_B;

        float acc[2][8][4];
        #pragma unroll
        for (int mt = 0; mt < 2; mt++)
            #pragma unroll
            for (int nt = 0; nt < 8; nt++)
                #pragma unroll
                for (int e = 0; e < 4; e++) acc[mt][nt][e] = 0.f;

        // ---- MMA mainloop with interleaved gather of next group ----
        #pragma unroll
        for (int s = 0; s < 9; s++) {
            const uint32_t a0s = tbase + a_off[0] + soff[s] * TILE_STRIDE;
            const uint32_t a1s = tbase + a_off[1] + soff[s] * TILE_STRIDE;
            const uint32_t bs  = b_addr + s * 128;
            #pragma unroll
            for (int c16 = 0; c16 < 4; c16++) {
                uint32_t af0[4], af1[4];
                ldsm_x4(af0, a0s + c16 * 32);
                ldsm_x4(af1, a1s + c16 * 32);
                uint32_t bf[16];
                #pragma unroll
                for (int j = 0; j < 4; j++)
                    ldsm_x4(bf + 4 * j, bs + j * 16 * (KP * 2) + c16 * 32);
                #pragma unroll
                for (int nt = 0; nt < 8; nt++) {
                    mma16816(acc[0][nt], af0, bf[nt * 2], bf[nt * 2 + 1]);
                    mma16816(acc[1][nt], af1, bf[nt * 2], bf[nt * 2 + 1]);
                }
            }
            if (has_next) {
                #pragma unroll
                for (int j = 0; j < 3; j++) {
                    int k = s * 3 + j;
                    if (k < 25) gather_chunk(smem, nxtbase, t, k, n0, n1, n2, n3);
                }
            }
        }

        // ---- epilogue: BN + ReLU + scatter ----
        const int gb = group * 4 + bidx;
        if (gb < nb) {
            int n  = __ldg(idx + gb * 3 + 0);
            int by = __ldg(idx + gb * 3 + 1);
            int bx = __ldg(idx + gb * 3 + 2);
            const int g  = lane >> 2;
            const int cc = (lane & 3) * 2;
            const float2* sc2 = reinterpret_cast<const float2*>(smem + SM_SC);
            const float2* bi2 = reinterpret_cast<const float2*>(smem + SM_BI);
            #pragma unroll
            for (int mt = 0; mt < 2; mt++) {
                int pos0 = mhalf * 32 + mt * 16 + g;
                int h0 = pos0 >> 3, w0 = pos0 & 7;
                float* op0 = out + (((n * HOUT + by * BST + h0) * WOUT) + bx * BST + w0) * CO;
                float* op1 = op0 + WOUT * CO;
                #pragma unroll
                for (int nt = 0; nt < 8; nt++) {
                    float2 s2 = sc2[nt * 4 + (lane & 3)];
                    float2 b2 = bi2[nt * 4 + (lane & 3)];
                    int col = nt * 8 + cc;
                    float2 o0, o1;
                    o0.x = fmaxf(fmaf(acc[mt][nt][0], s2.x, b2.x), 0.f);
                    o0.y = fmaxf(fmaf(acc[mt][nt][1], s2.y, b2.y), 0.f);
                    o1.x = fmaxf(fmaf(acc[mt][nt][2], s2.x, b2.x), 0.f);
                    o1.y = fmaxf(fmaf(acc[mt][nt][3], s2.y, b2.y), 0.f);
                    *reinterpret_cast<float2*>(op0 + col) = o0;
                    *reinterpret_cast<float2*>(op1 + col) = o1;
                }
            }
        }

        if (!has_next) break;
        __syncthreads();          // next buffer fully written, current fully read
        group = next;
        buf ^= 1;
    }
}

// ---------------------------------------------------------------------------
extern "C" void kernel_launch(void* const* d_in, const int* in_sizes, int n_in,
                              void* d_out, int out_size) {
    const float* x     = (const float*)d_in[0];
    const float* wgt   = (const float*)d_in[1];
    const float* convb = (const float*)d_in[2];
    const float* gamma = (const float*)d_in[3];
    const float* beta  = (const float*)d_in[4];
    const float* mean  = (const float*)d_in[5];
    const float* var   = (const float*)d_in[6];
    const int*   idx   = (const int*)d_in[7];
    const int nb = in_sizes[7] / 3;
    float* out = (float*)d_out;

    static bool attr_set = false;
    if (!attr_set) {
        cudaFuncSetAttribute(conv_kernel,
                             cudaFuncAttributeMaxDynamicSharedMemorySize, SMEM_TOTAL);
        attr_set = true;
    }

    wprep_kernel<<<(9 * 64 * 64 + 255) / 256, 256>>>(wgt);
    zero_kernel<<<4736, 256>>>(reinterpret_cast<float4*>(out), out_size >> 2);
    conv_kernel<<<148, 256, SMEM_TOTAL>>>(
        x, convb, gamma, beta, mean, var, idx, out, nb);
}